// round 14
// baseline (speedup 1.0000x reference)
#include <cuda_runtime.h>
#include <cuda_bf16.h>
#include <math.h>
#include <stdint.h>

#define B_ROWS 32768
#define D_IN   784
#define D_H    256
#define D_OUT  10
#define N_SEGS 20
#define SEG_E  50
#define PI_F   3.14159265358979323846f

// ---------------- scratch (static __device__ arrays: allocation-free) ----------------
__device__ float  g_z  [B_ROWS * D_H];
__device__ float  g_h2 [B_ROWS * D_H];
__device__ float2 g_He [N_SEGS * D_H];   // Hermitian-symmetrized (hr + i*hi)^50
__device__ float  g_p1 [2 * 512 * D_H];
__device__ float  g_p2 [2 * 512 * D_H];
__device__ float  g_mu1[D_H], g_rs1[D_H], g_mu2[D_H], g_rs2[D_H];
__device__ __align__(16) unsigned short g_Bhi[D_H * D_IN];
__device__ __align__(16) unsigned short g_Blo[D_H * D_IN];

// ---------------- packed f32x2 helpers ----------------
__device__ __forceinline__ float2 f2add(float2 a, float2 b) {
    union { float2 f; unsigned long long u; } A, B, R;
    A.f = a; B.f = b;
    asm("add.rn.f32x2 %0, %1, %2;" : "=l"(R.u) : "l"(A.u), "l"(B.u));
    return R.f;
}
__device__ __forceinline__ float2 f2mul(float2 a, float2 b) {
    union { float2 f; unsigned long long u; } A, B, R;
    A.f = a; B.f = b;
    asm("mul.rn.f32x2 %0, %1, %2;" : "=l"(R.u) : "l"(A.u), "l"(B.u));
    return R.f;
}
__device__ __forceinline__ float2 f2fma(float2 a, float2 b, float2 c) {
    union { float2 f; unsigned long long u; } A, B, C, R;
    A.f = a; B.f = b; C.f = c;
    asm("fma.rn.f32x2 %0, %1, %2, %3;" : "=l"(R.u) : "l"(A.u), "l"(B.u), "l"(C.u));
    return R.f;
}
__device__ __forceinline__ float2 f2sub(float2 a, float2 b) {
    union { float2 f; unsigned long long u; } A, B, R;
    A.f = a; B.f = b;
    const unsigned long long NEG1 = 0xBF800000BF800000ULL;
    asm("fma.rn.f32x2 %0, %1, %2, %3;" : "=l"(R.u) : "l"(B.u), "l"(NEG1), "l"(A.u));
    return R.f;
}

// ---------------- fast transcendentals ----------------
__device__ __forceinline__ float fast_atanh_over_x(float x) {
    float x2 = x * x;
    float small = 1.f + x2 * (1.f / 3.f) + x2 * x2 * 0.2f;
    float big = 0.5f * __logf(__fdividef(1.f + x, 1.f - x));
    big = __fdividef(big, x);
    return (x < 0.03f) ? small : big;
}
__device__ __forceinline__ float fast_tanh_over_x(float x) {
    float x2 = x * x;
    float small = 1.f - x2 * (1.f / 3.f) + x2 * x2 * (2.f / 15.f);
    float e = __expf(2.f * fminf(x, 15.f));
    float big = __fdividef(e - 1.f, (e + 1.f) * x);
    return (x < 0.03f) ? small : big;
}

// ------- merged prep: blocks 0-48 split W1; blocks 49-68 build Hs -------
__global__ void k_prep_all(const float* __restrict__ W1,
                           const float* __restrict__ Hr,
                           const float* __restrict__ Hi) {
    if (blockIdx.x < 49) {
        int n = threadIdx.x;
        int k0 = blockIdx.x * 16;
        unsigned short h[16], l[16];
        #pragma unroll
        for (int kk = 0; kk < 16; kk++) {
            float w = W1[(size_t)(k0 + kk) * D_H + n];
            __nv_bfloat16 bh = __float2bfloat16_rn(w);
            float r = w - __bfloat162float(bh);
            h[kk] = __bfloat16_as_ushort(bh);
            l[kk] = __bfloat16_as_ushort(__float2bfloat16_rn(r));
        }
        uint32_t* ph = (uint32_t*)(g_Bhi + (size_t)n * D_IN + k0);
        uint32_t* pl = (uint32_t*)(g_Blo + (size_t)n * D_IN + k0);
        #pragma unroll
        for (int j = 0; j < 8; j++) {
            ph[j] = (uint32_t)h[2*j] | ((uint32_t)h[2*j+1] << 16);
            pl[j] = (uint32_t)l[2*j] | ((uint32_t)l[2*j+1] << 16);
        }
    } else {
        __shared__ float2 E[D_H];
        int seg = blockIdx.x - 49, k = threadIdx.x;
        int i = seg * D_H + k;
        float br = Hr[i], bi = Hi[i], ar = 1.f, ai = 0.f;
        int e = SEG_E;
        while (e) {
            if (e & 1) { float t = ar*br - ai*bi; ai = ar*bi + ai*br; ar = t; }
            e >>= 1;
            if (e) { float t = br*br - bi*bi; bi = 2.f*br*bi; br = t; }
        }
        E[k] = make_float2(ar, ai);
        __syncthreads();
        float2 ek = E[k];
        float2 er = E[(D_H - k) & (D_H - 1)];
        g_He[i] = make_float2(0.5f * (ek.x + er.x), 0.5f * (ek.y - er.y));
    }
}

// ======================= mma.sync GEMM1 (+ fused BN1 partials) — R11 config ===========
#define RSTR 80
#define OFF_AHI 0
#define OFF_ALO 5120
#define OFF_BHI 10240
#define OFF_BLO 30720
#define STAGE   51200
#define SMEM_G  (2 * STAGE)
#define NPANEL  25

__device__ __forceinline__ void ldsm4(uint32_t* r, uint32_t a) {
    asm volatile("ldmatrix.sync.aligned.m8n8.x4.shared.b16 {%0,%1,%2,%3}, [%4];"
        : "=r"(r[0]), "=r"(r[1]), "=r"(r[2]), "=r"(r[3]) : "r"(a));
}
__device__ __forceinline__ void mma16816(float* c, const uint32_t* a, uint32_t b0, uint32_t b1) {
    asm volatile("mma.sync.aligned.m16n8k16.row.col.f32.bf16.bf16.f32 "
        "{%0,%1,%2,%3}, {%4,%5,%6,%7}, {%8,%9}, {%0,%1,%2,%3};"
        : "+f"(c[0]), "+f"(c[1]), "+f"(c[2]), "+f"(c[3])
        : "r"(a[0]), "r"(a[1]), "r"(a[2]), "r"(a[3]), "r"(b0), "r"(b1));
}
__device__ __forceinline__ uint32_t split2(float x, float y, uint32_t& lo) {
    __nv_bfloat16 hx = __float2bfloat16_rn(x), hy = __float2bfloat16_rn(y);
    __nv_bfloat16 lx = __float2bfloat16_rn(x - __bfloat162float(hx));
    __nv_bfloat16 ly = __float2bfloat16_rn(y - __bfloat162float(hy));
    lo = (uint32_t)__bfloat16_as_ushort(lx) | ((uint32_t)__bfloat16_as_ushort(ly) << 16);
    return (uint32_t)__bfloat16_as_ushort(hx) | ((uint32_t)__bfloat16_as_ushort(hy) << 16);
}
__device__ __forceinline__ uint32_t smem_u32(const void* p) {
    uint32_t a;
    asm("{ .reg .u64 t; cvta.to.shared.u64 t, %1; cvt.u32.u64 %0, t; }" : "=r"(a) : "l"(p));
    return a;
}

__global__ void __launch_bounds__(256, 1) k_gemm_mma(const float* __restrict__ A,
                                                     const float* __restrict__ bias) {
    extern __shared__ char sm[];
    uint32_t sbase = smem_u32(sm);
    int tid = threadIdx.x, warp = tid >> 5, lane = tid & 31;
    int wm = warp >> 2, wn = warp & 3;
    int gid = lane >> 2, tqd = lane & 3;

    const float* Ab = A + (size_t)blockIdx.x * 64 * D_IN;

    float c[2][8][4];
    #pragma unroll
    for (int mt = 0; mt < 2; mt++)
        #pragma unroll
        for (int nt = 0; nt < 8; nt++)
            #pragma unroll
            for (int r = 0; r < 4; r++) c[mt][nt][r] = 0.f;

    float4 pa[2];
    uint4  pbh[4], pbl[4];

    auto prefetch = [&](int p) {
        int k0 = p * 32, kw = (p < 24) ? 32 : 16;
        #pragma unroll
        for (int it = 0; it < 2; it++) {
            int idx = tid + 256 * it;
            int r = idx >> 3, c4 = (idx & 7) * 4;
            pa[it] = (c4 < kw) ? *(const float4*)(Ab + (size_t)r * D_IN + k0 + c4)
                               : make_float4(0.f, 0.f, 0.f, 0.f);
        }
        #pragma unroll
        for (int it = 0; it < 4; it++) {
            int idx = tid + 256 * it;
            int n = idx >> 2, j = idx & 3;
            if (j * 8 < kw) {
                pbh[it] = *(const uint4*)(g_Bhi + (size_t)n * D_IN + k0 + j * 8);
                pbl[it] = *(const uint4*)(g_Blo + (size_t)n * D_IN + k0 + j * 8);
            } else {
                pbh[it] = make_uint4(0, 0, 0, 0);
                pbl[it] = make_uint4(0, 0, 0, 0);
            }
        }
    };
    auto store_panel = [&](int b) {
        char* s = sm + b * STAGE;
        #pragma unroll
        for (int it = 0; it < 2; it++) {
            int idx = tid + 256 * it;
            int r = idx >> 3, c4 = (idx & 7) * 4;
            uint32_t l0, l1, h0, h1;
            h0 = split2(pa[it].x, pa[it].y, l0);
            h1 = split2(pa[it].z, pa[it].w, l1);
            uint32_t off = (uint32_t)(r * RSTR + c4 * 2);
            *(uint2*)(s + OFF_AHI + off) = make_uint2(h0, h1);
            *(uint2*)(s + OFF_ALO + off) = make_uint2(l0, l1);
        }
        #pragma unroll
        for (int it = 0; it < 4; it++) {
            int idx = tid + 256 * it;
            int n = idx >> 2, j = idx & 3;
            uint32_t off = (uint32_t)(n * RSTR + j * 16);
            *(uint4*)(s + OFF_BHI + off) = pbh[it];
            *(uint4*)(s + OFF_BLO + off) = pbl[it];
        }
    };
    auto mma_panel = [&](int b, int nks) {
        uint32_t base = sbase + b * STAGE;
        for (int ks = 0; ks < nks; ks++) {
            uint32_t ah[2][4], al[2][4];
            #pragma unroll
            for (int mt = 0; mt < 2; mt++) {
                uint32_t off = (uint32_t)((wm * 32 + mt * 16 + (lane & 15)) * RSTR
                                          + ks * 32 + ((lane >> 4) << 4));
                ldsm4(ah[mt], base + OFF_AHI + off);
                ldsm4(al[mt], base + OFF_ALO + off);
            }
            uint32_t bh[4][4], bl[4][4];
            #pragma unroll
            for (int q = 0; q < 4; q++) {
                int nrow = wn * 64 + q * 16 + (lane & 7) + ((lane >> 4) << 3);
                uint32_t off = (uint32_t)(nrow * RSTR + ks * 32 + (((lane >> 3) & 1) << 4));
                ldsm4(bh[q], base + OFF_BHI + off);
                ldsm4(bl[q], base + OFF_BLO + off);
            }
            #pragma unroll
            for (int mt = 0; mt < 2; mt++)
                #pragma unroll
                for (int q = 0; q < 4; q++) {
                    mma16816(c[mt][2*q],   ah[mt], bh[q][0], bh[q][1]);
                    mma16816(c[mt][2*q+1], ah[mt], bh[q][2], bh[q][3]);
                    mma16816(c[mt][2*q],   ah[mt], bl[q][0], bl[q][1]);
                    mma16816(c[mt][2*q+1], ah[mt], bl[q][2], bl[q][3]);
                    mma16816(c[mt][2*q],   al[mt], bh[q][0], bh[q][1]);
                    mma16816(c[mt][2*q+1], al[mt], bh[q][2], bh[q][3]);
                }
        }
    };

    prefetch(0);
    store_panel(0);
    __syncthreads();
    for (int p = 0; p < NPANEL; p++) {
        if (p + 1 < NPANEL) prefetch(p + 1);
        mma_panel(p & 1, (p < 24) ? 2 : 1);
        if (p + 1 < NPANEL) store_panel((p + 1) & 1);
        __syncthreads();
    }

    // epilogue: z = acc + bias, fused per-block BN1 column partials
    float* stS = (float*)sm;
    float* stQ = stS + 512;
    int rowb0 = blockIdx.x * 64 + wm * 32;
    #pragma unroll
    for (int nt = 0; nt < 8; nt++) {
        int col = wn * 64 + nt * 8 + tqd * 2;
        float bx = bias[col], by = bias[col + 1];
        float vs0 = 0.f, vs1 = 0.f, q0 = 0.f, q1 = 0.f;
        #pragma unroll
        for (int mt = 0; mt < 2; mt++) {
            int r0 = rowb0 + mt * 16 + gid;
            float v0 = c[mt][nt][0] + bx, v1 = c[mt][nt][1] + by;
            float v2 = c[mt][nt][2] + bx, v3 = c[mt][nt][3] + by;
            *(float2*)&g_z[(size_t)r0 * D_H + col]       = make_float2(v0, v1);
            *(float2*)&g_z[(size_t)(r0 + 8) * D_H + col] = make_float2(v2, v3);
            vs0 += v0 + v2; vs1 += v1 + v3;
            q0 += v0 * v0 + v2 * v2; q1 += v1 * v1 + v3 * v3;
        }
        #pragma unroll
        for (int m = 4; m <= 16; m <<= 1) {
            vs0 += __shfl_xor_sync(0xffffffffu, vs0, m);
            vs1 += __shfl_xor_sync(0xffffffffu, vs1, m);
            q0  += __shfl_xor_sync(0xffffffffu, q0,  m);
            q1  += __shfl_xor_sync(0xffffffffu, q1,  m);
        }
        if (gid == 0) {
            stS[wm * 256 + col] = vs0; stS[wm * 256 + col + 1] = vs1;
            stQ[wm * 256 + col] = q0;  stQ[wm * 256 + col + 1] = q1;
        }
    }
    __syncthreads();
    if (tid < 256) {
        g_p1[(size_t)blockIdx.x * D_H + tid]         = stS[tid] + stS[256 + tid];
        g_p1[(size_t)(512 + blockIdx.x) * D_H + tid] = stQ[tid] + stQ[256 + tid];
    }
}

// ---------------- BN2 column-stat partials over h2 ----------------
__global__ void k_stats2() {
    int col = threadIdx.x, b = blockIdx.x;
    float s = 0.f, q = 0.f;
    const float* p = g_h2 + (size_t)b * 128 * D_H + col;
    for (int r = 0; r < 128; r++) { float v = p[(size_t)r * D_H]; s += v; q += v * v; }
    g_p2[b * D_H + col]         = s;
    g_p2[(256 + b) * D_H + col] = q;
}

// ---------------- fused deterministic BN reduce (single launch) ----------------
__global__ void k_bnreduce(int which, int nblk) {
    __shared__ float sS[4][D_H], sQ[4][D_H];
    const float* part = (which == 1) ? g_p1 : g_p2;
    int col = threadIdx.x & 255, grp = threadIdx.x >> 8;
    int per = nblk / 4;
    float s = 0.f, q = 0.f;
    for (int b = grp * per; b < (grp + 1) * per; b++) {
        s += part[b * D_H + col];
        q += part[(nblk + b) * D_H + col];
    }
    sS[grp][col] = s; sQ[grp][col] = q;
    __syncthreads();
    if (threadIdx.x < 256) {
        float S = sS[0][col] + sS[1][col] + sS[2][col] + sS[3][col];
        float Q = sQ[0][col] + sQ[1][col] + sQ[2][col] + sQ[3][col];
        float m   = S * (1.0f / B_ROWS);
        float var = Q * (1.0f / B_ROWS) - m * m;
        float rs  = rsqrtf(var + 1e-5f);
        if (which == 1) { g_mu1[col] = m; g_rs1[col] = rs; }
        else            { g_mu2[col] = m; g_rs2[col] = rs; }
    }
}

// ---------------- complex helpers ----------------
__device__ __forceinline__ float2 c_mul(float2 a, float2 b){ return make_float2(a.x*b.x - a.y*b.y, a.x*b.y + a.y*b.x); }

template <int S>
__device__ __forceinline__ float2 c_muli(float2 a) {
    return (S > 0) ? make_float2(-a.y, a.x) : make_float2(a.y, -a.x);
}

template <int S>
__device__ __forceinline__ void fft8(float2 v[8]) {
    const float RH = 0.70710678118654752f;
    float2 e0, e1, e2, e3, o0, o1, o2, o3;
    {
        float2 t0 = f2add(v[0], v[4]), t1 = f2sub(v[0], v[4]);
        float2 t2 = f2add(v[2], v[6]), t3 = f2sub(v[2], v[6]);
        float2 r  = c_muli<S>(t3);
        e0 = f2add(t0, t2); e2 = f2sub(t0, t2); e1 = f2add(t1, r); e3 = f2sub(t1, r);
    }
    {
        float2 t0 = f2add(v[1], v[5]), t1 = f2sub(v[1], v[5]);
        float2 t2 = f2add(v[3], v[7]), t3 = f2sub(v[3], v[7]);
        float2 r  = c_muli<S>(t3);
        o0 = f2add(t0, t2); o2 = f2sub(t0, t2); o1 = f2add(t1, r); o3 = f2sub(t1, r);
    }
    const float2 w1 = make_float2(RH,  (S > 0) ? RH : -RH);
    const float2 w3 = make_float2(-RH, (S > 0) ? RH : -RH);
    float2 a;
    v[0] = f2add(e0, o0); v[4] = f2sub(e0, o0);
    a = c_mul(o1, w1);    v[1] = f2add(e1, a); v[5] = f2sub(e1, a);
    a = c_muli<S>(o2);    v[2] = f2add(e2, a); v[6] = f2sub(e2, a);
    a = c_mul(o3, w3);    v[3] = f2add(e3, a); v[7] = f2sub(e3, a);
}

__device__ __forceinline__ float2 shflx2(float2 v, int m) {
    v.x = __shfl_xor_sync(0xffffffffu, v.x, m);
    v.y = __shfl_xor_sync(0xffffffffu, v.y, m);
    return v;
}

__device__ __forceinline__ void dif_stage(float2 x[8], int m, float2 w, bool up) {
    #pragma unroll
    for (int r = 0; r < 8; r++) {
        float2 o = shflx2(x[r], m);
        x[r] = up ? c_mul(f2sub(o, x[r]), w) : f2add(x[r], o);
    }
}
__device__ __forceinline__ void stage_m1(float2 x[8], bool up) {
    #pragma unroll
    for (int r = 0; r < 8; r++) {
        float2 o = shflx2(x[r], 1);
        x[r] = up ? f2sub(o, x[r]) : f2add(x[r], o);
    }
}
__device__ __forceinline__ void dit_stage(float2 x[8], int m, float2 wc, bool up) {
    #pragma unroll
    for (int r = 0; r < 8; r++) {
        float2 o  = shflx2(x[r], m);
        float2 vw = c_mul(up ? x[r] : o, wc);
        x[r] = up ? f2sub(o, vw) : f2add(x[r], vw);
    }
}

__device__ __forceinline__ void wsum4(float& a, float& b, float& c, float& d) {
    #pragma unroll
    for (int m = 16; m; m >>= 1) {
        a += __shfl_xor_sync(0xffffffffu, a, m);
        b += __shfl_xor_sync(0xffffffffu, b, m);
        c += __shfl_xor_sync(0xffffffffu, c, m);
        d += __shfl_xor_sync(0xffffffffu, d, m);
    }
}

// ---- scan: FFT once -> per-row spectra A,B -> 20 shuffle-free diagonal segments -> IFFT ----
// RPW=4 (grid 1024) for finer wave granularity.
#define RPW 4
#define SCAN_WARPS 8
__global__ void __launch_bounds__(256, 2) k_scan(const float* __restrict__ g1,
                                                 const float* __restrict__ be1,
                                                 const float* __restrict__ alphas,
                                                 const float* __restrict__ betas) {
    int warp = threadIdx.x >> 5, lane = threadIdx.x & 31;
    int row0 = (blockIdx.x * SCAN_WARPS + warp) * RPW;
    int rl = __brev((unsigned)lane) >> 27;
    const float sc = 0.031622776601683793f;

    int mrl   = (32 - rl) & 31;
    int mlane = (int)(__brev((unsigned)mrl) >> 27);

    bool u1 = (lane & 1), u2 = (lane & 2), u4 = (lane & 4), u8 = (lane & 8), u16 = (lane & 16);

    float gg[8], bb[8];
    #pragma unroll
    for (int r = 0; r < 8; r++) {
        int c = lane + 32 * r;
        gg[r] = g1[c] * g_rs1[c];
        bb[r] = be1[c] - g1[c] * g_mu1[c] * g_rs1[c];
    }

    for (int pr = 0; pr < RPW / 2; pr++) {
        int rowa = row0 + 2 * pr, rowb = rowa + 1;
        float2 A[8], B[8];
        {
            float2 Z[8];
            #pragma unroll
            for (int r = 0; r < 8; r++) {
                int c = lane + 32 * r;
                float va = fmaxf(gg[r] * g_z[(size_t)rowa * D_H + c] + bb[r], 0.f);
                float vb = fmaxf(gg[r] * g_z[(size_t)rowb * D_H + c] + bb[r], 0.f);
                Z[r] = make_float2(va, vb);
            }
            // forward 256-pt FFT (twiddles scoped)
            {
                float2 W2t, W4t, W8t, W16t, Tf[8];
                float a;
                a = -2.f * PI_F * (float)(lane & 1)  / 4.f;   W2t  = make_float2(cosf(a), sinf(a));
                a = -2.f * PI_F * (float)(lane & 3)  / 8.f;   W4t  = make_float2(cosf(a), sinf(a));
                a = -2.f * PI_F * (float)(lane & 7)  / 16.f;  W8t  = make_float2(cosf(a), sinf(a));
                a = -2.f * PI_F * (float)(lane & 15) / 32.f;  W16t = make_float2(cosf(a), sinf(a));
                #pragma unroll
                for (int r = 0; r < 8; r++) {
                    float t = -2.f * PI_F * (float)(lane * r) / 256.f;
                    Tf[r] = make_float2(cosf(t), sinf(t));
                }
                fft8<-1>(Z);
                #pragma unroll
                for (int r = 0; r < 8; r++) Z[r] = c_mul(Z[r], Tf[r]);
                dif_stage(Z, 16, W16t, u16);
                dif_stage(Z, 8,  W8t,  u8);
                dif_stage(Z, 4,  W4t,  u4);
                dif_stage(Z, 2,  W2t,  u2);
                stage_m1(Z, u1);
            }
            // split into per-row spectra (mirror shuffles ONCE)
            float2 Zc[8];
            {
                float tx = __shfl_sync(0xffffffffu, Z[0].x, mlane);
                float ty = __shfl_sync(0xffffffffu, Z[0].y, mlane);
                Zc[0] = make_float2(tx, -ty);
            }
            #pragma unroll
            for (int r = 1; r < 8; r++) {
                float2 t = shflx2(Z[8 - r], 31);
                Zc[r] = make_float2(t.x, -t.y);
            }
            #pragma unroll
            for (int r = 0; r < 8; r++) {
                A[r] = make_float2(0.5f * (Z[r].x + Zc[r].x), 0.5f * (Z[r].y + Zc[r].y));
                float dx = Z[r].x - Zc[r].x, dy = Z[r].y - Zc[r].y;
                B[r] = make_float2(0.5f * dy, -0.5f * dx);     // -i*(Z-Zc)/2
            }
        }

        // ---- 20 diagonal segments: per-lane only (except wsum4) ----
        for (int seg = 0; seg < N_SEGS; seg++) {
            float2 Hs[8];
            float  H2[8];
            const float4* Hp = (const float4*)(g_He + seg * D_H + 8 * rl);
            #pragma unroll
            for (int r4 = 0; r4 < 4; r4++) {
                float4 hv = __ldg(Hp + r4);
                Hs[2 * r4]     = make_float2(hv.x, hv.y);
                Hs[2 * r4 + 1] = make_float2(hv.z, hv.w);
                H2[2 * r4]     = hv.x * hv.x + hv.y * hv.y;
                H2[2 * r4 + 1] = hv.z * hv.z + hv.w * hv.w;
            }

            float2 sa = make_float2(0.f, 0.f), ta = make_float2(0.f, 0.f);
            float2 sb = make_float2(0.f, 0.f), tb = make_float2(0.f, 0.f);
            #pragma unroll
            for (int r = 0; r < 8; r++) {
                float2 pa = f2mul(A[r], A[r]);
                float2 pb = f2mul(B[r], B[r]);
                float2 h2p = make_float2(H2[r], H2[r]);
                sa = f2add(sa, pa);
                sb = f2add(sb, pb);
                ta = f2fma(pa, h2p, ta);
                tb = f2fma(pb, h2p, tb);
            }
            float SA = sa.x + sa.y, TA = ta.x + ta.y;
            float SB = sb.x + sb.y, TB = tb.x + tb.y;
            wsum4(SA, TA, SB, TB);

            float na2 = SA * (1.f / 256.f);
            float ca2 = TA * (1.f / 256.f);
            float nb2 = SB * (1.f / 256.f);
            float cb2 = TB * (1.f / 256.f);

            float sna = fminf(fmaxf(sc * sqrtf(na2), 1e-12f), 1.f - 1e-5f);
            float snb = fminf(fmaxf(sc * sqrtf(nb2), 1e-12f), 1.f - 1e-5f);
            float sla = fast_atanh_over_x(sna);
            float slb = fast_atanh_over_x(snb);

            float snva = fmaxf(sc * sla * sqrtf(ca2), 1e-12f);
            float snvb = fmaxf(sc * slb * sqrtf(cb2), 1e-12f);
            float sea = fast_tanh_over_x(snva);
            float seb = fast_tanh_over_x(snvb);

            float al = __ldg(alphas + seg), bt = __ldg(betas + seg);
            float ga = al * sea * sla;
            float gb = al * seb * slb;

            #pragma unroll
            for (int r = 0; r < 8; r++) {
                float2 Ka = make_float2(fmaf(ga, Hs[r].x, bt), ga * Hs[r].y);
                float2 Kb = make_float2(fmaf(gb, Hs[r].x, bt), gb * Hs[r].y);
                A[r] = c_mul(Ka, A[r]);
                B[r] = c_mul(Kb, B[r]);
            }
        }

        // ---- recombine Z = A + iB, inverse FFT, store ----
        {
            float2 Z[8];
            #pragma unroll
            for (int r = 0; r < 8; r++)
                Z[r] = make_float2(A[r].x - B[r].y, A[r].y + B[r].x);

            float2 W2t, W4t, W8t, W16t, Tf[8];
            float a;
            a = 2.f * PI_F * (float)(lane & 1)  / 4.f;   W2t  = make_float2(cosf(a), sinf(a));
            a = 2.f * PI_F * (float)(lane & 3)  / 8.f;   W4t  = make_float2(cosf(a), sinf(a));
            a = 2.f * PI_F * (float)(lane & 7)  / 16.f;  W8t  = make_float2(cosf(a), sinf(a));
            a = 2.f * PI_F * (float)(lane & 15) / 32.f;  W16t = make_float2(cosf(a), sinf(a));
            #pragma unroll
            for (int r = 0; r < 8; r++) {
                float t = 2.f * PI_F * (float)(lane * r) / 256.f;
                Tf[r] = make_float2(cosf(t), sinf(t));
            }
            stage_m1(Z, u1);
            dit_stage(Z, 2,  W2t,  u2);
            dit_stage(Z, 4,  W4t,  u4);
            dit_stage(Z, 8,  W8t,  u8);
            dit_stage(Z, 16, W16t, u16);
            #pragma unroll
            for (int r = 0; r < 8; r++) Z[r] = c_mul(Z[r], Tf[r]);
            fft8<1>(Z);

            const float2 i256 = make_float2(1.f / 256.f, 1.f / 256.f);
            #pragma unroll
            for (int r = 0; r < 8; r++) {
                float2 hp = f2mul(Z[r], i256);
                int c = lane + 32 * r;
                g_h2[(size_t)rowa * D_H + c] = hp.x;
                g_h2[(size_t)rowb * D_H + c] = hp.y;
            }
        }
    }
}

// ---------------- final: out = relu(BN2(h2)) @ W2 + b2 ----------------
__global__ __launch_bounds__(256) void k_out(const float* __restrict__ g2,
                                             const float* __restrict__ be2,
                                             const float* __restrict__ W2,
                                             const float* __restrict__ b2,
                                             float* __restrict__ out) {
    __shared__ float sW[D_H * D_OUT];
    for (int i = threadIdx.x; i < D_H * D_OUT; i += 256) sW[i] = W2[i];
    __syncthreads();
    int warp = threadIdx.x >> 5, lane = threadIdx.x & 31;
    int row = blockIdx.x * 8 + warp;
    float acc[D_OUT];
    #pragma unroll
    for (int o = 0; o < D_OUT; o++) acc[o] = 0.f;
    #pragma unroll
    for (int r = 0; r < 8; r++) {
        int c = lane + 32 * r;
        float hv = g_h2[(size_t)row * D_H + c];
        float a  = fmaxf(g2[c] * (hv - g_mu2[c]) * g_rs2[c] + be2[c], 0.f);
        #pragma unroll
        for (int o = 0; o < D_OUT; o++) acc[o] += a * sW[c * D_OUT + o];
    }
    #pragma unroll
    for (int o = 0; o < D_OUT; o++) {
        #pragma unroll
        for (int m = 16; m; m >>= 1) acc[o] += __shfl_xor_sync(0xffffffffu, acc[o], m);
    }
    if (lane < D_OUT) out[(size_t)row * D_OUT + lane] = acc[lane] + b2[lane];
}

// ---------------- launch ----------------
extern "C" void kernel_launch(void* const* d_in, const int* in_sizes, int n_in,
                              void* d_out, int out_size) {
    const float* x   = (const float*)d_in[0];
    const float* W1  = (const float*)d_in[1];
    const float* b1  = (const float*)d_in[2];
    const float* g1  = (const float*)d_in[3];
    const float* be1 = (const float*)d_in[4];
    const float* Hr  = (const float*)d_in[5];
    const float* Hi  = (const float*)d_in[6];
    const float* al  = (const float*)d_in[7];
    const float* bt  = (const float*)d_in[8];
    const float* g2  = (const float*)d_in[9];
    const float* be2 = (const float*)d_in[10];
    const float* W2  = (const float*)d_in[11];
    const float* b2  = (const float*)d_in[12];
    float* out = (float*)d_out;

    cudaFuncSetAttribute(k_gemm_mma, cudaFuncAttributeMaxDynamicSharedMemorySize, SMEM_G);

    k_prep_all<<<49 + N_SEGS, D_H>>>(W1, Hr, Hi);            // launch 1
    k_gemm_mma<<<B_ROWS / 64, 256, SMEM_G>>>(x, b1);         // launch 2
    k_bnreduce<<<1, 1024>>>(1, 512);                         // launch 3
    k_scan<<<B_ROWS / (SCAN_WARPS * RPW), 256>>>(g1, be1, al, bt);  // launch 4 (captured)
    k_stats2<<<256, 256>>>();                                // launch 5
    k_bnreduce<<<1, 1024>>>(2, 256);                         // launch 6
    k_out<<<B_ROWS / 8, 256>>>(g2, be2, W2, b2, out);        // launch 7
}

// round 15
// speedup vs baseline: 1.0663x; 1.0663x over previous
#include <cuda_runtime.h>
#include <cuda_bf16.h>
#include <math.h>
#include <stdint.h>

#define B_ROWS 32768
#define D_IN   784
#define D_H    256
#define D_OUT  10
#define N_SEGS 20
#define SEG_E  50
#define PI_F   3.14159265358979323846f

// ---------------- scratch (static __device__ arrays: allocation-free) ----------------
__device__ float  g_z  [B_ROWS * D_H];
__device__ float  g_h2 [B_ROWS * D_H];
__device__ float2 g_He [N_SEGS * D_H];   // Hermitian-symmetrized (hr + i*hi)^50
__device__ float  g_p1 [2 * 512 * D_H];
__device__ float  g_p2 [2 * 512 * D_H];
__device__ float  g_mu1[D_H], g_rs1[D_H], g_mu2[D_H], g_rs2[D_H];
__device__ __align__(16) unsigned short g_Bhi[D_H * D_IN];
__device__ __align__(16) unsigned short g_Blo[D_H * D_IN];

// ---------------- packed f32x2 helpers ----------------
__device__ __forceinline__ float2 f2add(float2 a, float2 b) {
    union { float2 f; unsigned long long u; } A, B, R;
    A.f = a; B.f = b;
    asm("add.rn.f32x2 %0, %1, %2;" : "=l"(R.u) : "l"(A.u), "l"(B.u));
    return R.f;
}
__device__ __forceinline__ float2 f2mul(float2 a, float2 b) {
    union { float2 f; unsigned long long u; } A, B, R;
    A.f = a; B.f = b;
    asm("mul.rn.f32x2 %0, %1, %2;" : "=l"(R.u) : "l"(A.u), "l"(B.u));
    return R.f;
}
__device__ __forceinline__ float2 f2fma(float2 a, float2 b, float2 c) {
    union { float2 f; unsigned long long u; } A, B, C, R;
    A.f = a; B.f = b; C.f = c;
    asm("fma.rn.f32x2 %0, %1, %2, %3;" : "=l"(R.u) : "l"(A.u), "l"(B.u), "l"(C.u));
    return R.f;
}
__device__ __forceinline__ float2 f2sub(float2 a, float2 b) {
    union { float2 f; unsigned long long u; } A, B, R;
    A.f = a; B.f = b;
    const unsigned long long NEG1 = 0xBF800000BF800000ULL;
    asm("fma.rn.f32x2 %0, %1, %2, %3;" : "=l"(R.u) : "l"(B.u), "l"(NEG1), "l"(A.u));
    return R.f;
}

// ---------------- fast transcendentals ----------------
__device__ __forceinline__ float fast_atanh_over_x(float x) {
    float x2 = x * x;
    float small = 1.f + x2 * (1.f / 3.f) + x2 * x2 * 0.2f;
    float big = 0.5f * __logf(__fdividef(1.f + x, 1.f - x));
    big = __fdividef(big, x);
    return (x < 0.03f) ? small : big;
}
__device__ __forceinline__ float fast_tanh_over_x(float x) {
    float x2 = x * x;
    float small = 1.f - x2 * (1.f / 3.f) + x2 * x2 * (2.f / 15.f);
    float e = __expf(2.f * fminf(x, 15.f));
    float big = __fdividef(e - 1.f, (e + 1.f) * x);
    return (x < 0.03f) ? small : big;
}

// ------- merged prep: blocks 0-48 split W1; blocks 49-68 build Hs -------
__global__ void k_prep_all(const float* __restrict__ W1,
                           const float* __restrict__ Hr,
                           const float* __restrict__ Hi) {
    if (blockIdx.x < 49) {
        int n = threadIdx.x;
        int k0 = blockIdx.x * 16;
        unsigned short h[16], l[16];
        #pragma unroll
        for (int kk = 0; kk < 16; kk++) {
            float w = W1[(size_t)(k0 + kk) * D_H + n];
            __nv_bfloat16 bh = __float2bfloat16_rn(w);
            float r = w - __bfloat162float(bh);
            h[kk] = __bfloat16_as_ushort(bh);
            l[kk] = __bfloat16_as_ushort(__float2bfloat16_rn(r));
        }
        uint32_t* ph = (uint32_t*)(g_Bhi + (size_t)n * D_IN + k0);
        uint32_t* pl = (uint32_t*)(g_Blo + (size_t)n * D_IN + k0);
        #pragma unroll
        for (int j = 0; j < 8; j++) {
            ph[j] = (uint32_t)h[2*j] | ((uint32_t)h[2*j+1] << 16);
            pl[j] = (uint32_t)l[2*j] | ((uint32_t)l[2*j+1] << 16);
        }
    } else {
        __shared__ float2 E[D_H];
        int seg = blockIdx.x - 49, k = threadIdx.x;
        int i = seg * D_H + k;
        float br = Hr[i], bi = Hi[i], ar = 1.f, ai = 0.f;
        int e = SEG_E;
        while (e) {
            if (e & 1) { float t = ar*br - ai*bi; ai = ar*bi + ai*br; ar = t; }
            e >>= 1;
            if (e) { float t = br*br - bi*bi; bi = 2.f*br*bi; br = t; }
        }
        E[k] = make_float2(ar, ai);
        __syncthreads();
        float2 ek = E[k];
        float2 er = E[(D_H - k) & (D_H - 1)];
        g_He[i] = make_float2(0.5f * (ek.x + er.x), 0.5f * (ek.y - er.y));
    }
}

// ======================= mma.sync GEMM1 (+ fused BN1 partials) — R11 config ===========
#define RSTR 80
#define OFF_AHI 0
#define OFF_ALO 5120
#define OFF_BHI 10240
#define OFF_BLO 30720
#define STAGE   51200
#define SMEM_G  (2 * STAGE)
#define NPANEL  25

__device__ __forceinline__ void ldsm4(uint32_t* r, uint32_t a) {
    asm volatile("ldmatrix.sync.aligned.m8n8.x4.shared.b16 {%0,%1,%2,%3}, [%4];"
        : "=r"(r[0]), "=r"(r[1]), "=r"(r[2]), "=r"(r[3]) : "r"(a));
}
__device__ __forceinline__ void mma16816(float* c, const uint32_t* a, uint32_t b0, uint32_t b1) {
    asm volatile("mma.sync.aligned.m16n8k16.row.col.f32.bf16.bf16.f32 "
        "{%0,%1,%2,%3}, {%4,%5,%6,%7}, {%8,%9}, {%0,%1,%2,%3};"
        : "+f"(c[0]), "+f"(c[1]), "+f"(c[2]), "+f"(c[3])
        : "r"(a[0]), "r"(a[1]), "r"(a[2]), "r"(a[3]), "r"(b0), "r"(b1));
}
__device__ __forceinline__ uint32_t split2(float x, float y, uint32_t& lo) {
    __nv_bfloat16 hx = __float2bfloat16_rn(x), hy = __float2bfloat16_rn(y);
    __nv_bfloat16 lx = __float2bfloat16_rn(x - __bfloat162float(hx));
    __nv_bfloat16 ly = __float2bfloat16_rn(y - __bfloat162float(hy));
    lo = (uint32_t)__bfloat16_as_ushort(lx) | ((uint32_t)__bfloat16_as_ushort(ly) << 16);
    return (uint32_t)__bfloat16_as_ushort(hx) | ((uint32_t)__bfloat16_as_ushort(hy) << 16);
}
__device__ __forceinline__ uint32_t smem_u32(const void* p) {
    uint32_t a;
    asm("{ .reg .u64 t; cvta.to.shared.u64 t, %1; cvt.u32.u64 %0, t; }" : "=r"(a) : "l"(p));
    return a;
}

__global__ void __launch_bounds__(256, 1) k_gemm_mma(const float* __restrict__ A,
                                                     const float* __restrict__ bias) {
    extern __shared__ char sm[];
    uint32_t sbase = smem_u32(sm);
    int tid = threadIdx.x, warp = tid >> 5, lane = tid & 31;
    int wm = warp >> 2, wn = warp & 3;
    int gid = lane >> 2, tqd = lane & 3;

    const float* Ab = A + (size_t)blockIdx.x * 64 * D_IN;

    float c[2][8][4];
    #pragma unroll
    for (int mt = 0; mt < 2; mt++)
        #pragma unroll
        for (int nt = 0; nt < 8; nt++)
            #pragma unroll
            for (int r = 0; r < 4; r++) c[mt][nt][r] = 0.f;

    float4 pa[2];
    uint4  pbh[4], pbl[4];

    auto prefetch = [&](int p) {
        int k0 = p * 32, kw = (p < 24) ? 32 : 16;
        #pragma unroll
        for (int it = 0; it < 2; it++) {
            int idx = tid + 256 * it;
            int r = idx >> 3, c4 = (idx & 7) * 4;
            pa[it] = (c4 < kw) ? *(const float4*)(Ab + (size_t)r * D_IN + k0 + c4)
                               : make_float4(0.f, 0.f, 0.f, 0.f);
        }
        #pragma unroll
        for (int it = 0; it < 4; it++) {
            int idx = tid + 256 * it;
            int n = idx >> 2, j = idx & 3;
            if (j * 8 < kw) {
                pbh[it] = *(const uint4*)(g_Bhi + (size_t)n * D_IN + k0 + j * 8);
                pbl[it] = *(const uint4*)(g_Blo + (size_t)n * D_IN + k0 + j * 8);
            } else {
                pbh[it] = make_uint4(0, 0, 0, 0);
                pbl[it] = make_uint4(0, 0, 0, 0);
            }
        }
    };
    auto store_panel = [&](int b) {
        char* s = sm + b * STAGE;
        #pragma unroll
        for (int it = 0; it < 2; it++) {
            int idx = tid + 256 * it;
            int r = idx >> 3, c4 = (idx & 7) * 4;
            uint32_t l0, l1, h0, h1;
            h0 = split2(pa[it].x, pa[it].y, l0);
            h1 = split2(pa[it].z, pa[it].w, l1);
            uint32_t off = (uint32_t)(r * RSTR + c4 * 2);
            *(uint2*)(s + OFF_AHI + off) = make_uint2(h0, h1);
            *(uint2*)(s + OFF_ALO + off) = make_uint2(l0, l1);
        }
        #pragma unroll
        for (int it = 0; it < 4; it++) {
            int idx = tid + 256 * it;
            int n = idx >> 2, j = idx & 3;
            uint32_t off = (uint32_t)(n * RSTR + j * 16);
            *(uint4*)(s + OFF_BHI + off) = pbh[it];
            *(uint4*)(s + OFF_BLO + off) = pbl[it];
        }
    };
    auto mma_panel = [&](int b, int nks) {
        uint32_t base = sbase + b * STAGE;
        for (int ks = 0; ks < nks; ks++) {
            uint32_t ah[2][4], al[2][4];
            #pragma unroll
            for (int mt = 0; mt < 2; mt++) {
                uint32_t off = (uint32_t)((wm * 32 + mt * 16 + (lane & 15)) * RSTR
                                          + ks * 32 + ((lane >> 4) << 4));
                ldsm4(ah[mt], base + OFF_AHI + off);
                ldsm4(al[mt], base + OFF_ALO + off);
            }
            uint32_t bh[4][4], bl[4][4];
            #pragma unroll
            for (int q = 0; q < 4; q++) {
                int nrow = wn * 64 + q * 16 + (lane & 7) + ((lane >> 4) << 3);
                uint32_t off = (uint32_t)(nrow * RSTR + ks * 32 + (((lane >> 3) & 1) << 4));
                ldsm4(bh[q], base + OFF_BHI + off);
                ldsm4(bl[q], base + OFF_BLO + off);
            }
            #pragma unroll
            for (int mt = 0; mt < 2; mt++)
                #pragma unroll
                for (int q = 0; q < 4; q++) {
                    mma16816(c[mt][2*q],   ah[mt], bh[q][0], bh[q][1]);
                    mma16816(c[mt][2*q+1], ah[mt], bh[q][2], bh[q][3]);
                    mma16816(c[mt][2*q],   ah[mt], bl[q][0], bl[q][1]);
                    mma16816(c[mt][2*q+1], ah[mt], bl[q][2], bl[q][3]);
                    mma16816(c[mt][2*q],   al[mt], bh[q][0], bh[q][1]);
                    mma16816(c[mt][2*q+1], al[mt], bh[q][2], bh[q][3]);
                }
        }
    };

    prefetch(0);
    store_panel(0);
    __syncthreads();
    for (int p = 0; p < NPANEL; p++) {
        if (p + 1 < NPANEL) prefetch(p + 1);
        mma_panel(p & 1, (p < 24) ? 2 : 1);
        if (p + 1 < NPANEL) store_panel((p + 1) & 1);
        __syncthreads();
    }

    float* stS = (float*)sm;
    float* stQ = stS + 512;
    int rowb0 = blockIdx.x * 64 + wm * 32;
    #pragma unroll
    for (int nt = 0; nt < 8; nt++) {
        int col = wn * 64 + nt * 8 + tqd * 2;
        float bx = bias[col], by = bias[col + 1];
        float vs0 = 0.f, vs1 = 0.f, q0 = 0.f, q1 = 0.f;
        #pragma unroll
        for (int mt = 0; mt < 2; mt++) {
            int r0 = rowb0 + mt * 16 + gid;
            float v0 = c[mt][nt][0] + bx, v1 = c[mt][nt][1] + by;
            float v2 = c[mt][nt][2] + bx, v3 = c[mt][nt][3] + by;
            *(float2*)&g_z[(size_t)r0 * D_H + col]       = make_float2(v0, v1);
            *(float2*)&g_z[(size_t)(r0 + 8) * D_H + col] = make_float2(v2, v3);
            vs0 += v0 + v2; vs1 += v1 + v3;
            q0 += v0 * v0 + v2 * v2; q1 += v1 * v1 + v3 * v3;
        }
        #pragma unroll
        for (int m = 4; m <= 16; m <<= 1) {
            vs0 += __shfl_xor_sync(0xffffffffu, vs0, m);
            vs1 += __shfl_xor_sync(0xffffffffu, vs1, m);
            q0  += __shfl_xor_sync(0xffffffffu, q0,  m);
            q1  += __shfl_xor_sync(0xffffffffu, q1,  m);
        }
        if (gid == 0) {
            stS[wm * 256 + col] = vs0; stS[wm * 256 + col + 1] = vs1;
            stQ[wm * 256 + col] = q0;  stQ[wm * 256 + col + 1] = q1;
        }
    }
    __syncthreads();
    if (tid < 256) {
        g_p1[(size_t)blockIdx.x * D_H + tid]         = stS[tid] + stS[256 + tid];
        g_p1[(size_t)(512 + blockIdx.x) * D_H + tid] = stQ[tid] + stQ[256 + tid];
    }
}

// ---------------- BN2 column-stat partials over h2 ----------------
__global__ void k_stats2() {
    int col = threadIdx.x, b = blockIdx.x;
    float s = 0.f, q = 0.f;
    const float* p = g_h2 + (size_t)b * 128 * D_H + col;
    for (int r = 0; r < 128; r++) { float v = p[(size_t)r * D_H]; s += v; q += v * v; }
    g_p2[b * D_H + col]         = s;
    g_p2[(256 + b) * D_H + col] = q;
}

// ---------------- fused deterministic BN reduce (single launch) ----------------
__global__ void k_bnreduce(int which, int nblk) {
    __shared__ float sS[4][D_H], sQ[4][D_H];
    const float* part = (which == 1) ? g_p1 : g_p2;
    int col = threadIdx.x & 255, grp = threadIdx.x >> 8;
    int per = nblk / 4;
    float s = 0.f, q = 0.f;
    for (int b = grp * per; b < (grp + 1) * per; b++) {
        s += part[b * D_H + col];
        q += part[(nblk + b) * D_H + col];
    }
    sS[grp][col] = s; sQ[grp][col] = q;
    __syncthreads();
    if (threadIdx.x < 256) {
        float S = sS[0][col] + sS[1][col] + sS[2][col] + sS[3][col];
        float Q = sQ[0][col] + sQ[1][col] + sQ[2][col] + sQ[3][col];
        float m   = S * (1.0f / B_ROWS);
        float var = Q * (1.0f / B_ROWS) - m * m;
        float rs  = rsqrtf(var + 1e-5f);
        if (which == 1) { g_mu1[col] = m; g_rs1[col] = rs; }
        else            { g_mu2[col] = m; g_rs2[col] = rs; }
    }
}

// ---------------- complex helpers ----------------
__device__ __forceinline__ float2 c_mul(float2 a, float2 b){ return make_float2(a.x*b.x - a.y*b.y, a.x*b.y + a.y*b.x); }

template <int S>
__device__ __forceinline__ float2 c_muli(float2 a) {
    return (S > 0) ? make_float2(-a.y, a.x) : make_float2(a.y, -a.x);
}

template <int S>
__device__ __forceinline__ void fft8(float2 v[8]) {
    const float RH = 0.70710678118654752f;
    float2 e0, e1, e2, e3, o0, o1, o2, o3;
    {
        float2 t0 = f2add(v[0], v[4]), t1 = f2sub(v[0], v[4]);
        float2 t2 = f2add(v[2], v[6]), t3 = f2sub(v[2], v[6]);
        float2 r  = c_muli<S>(t3);
        e0 = f2add(t0, t2); e2 = f2sub(t0, t2); e1 = f2add(t1, r); e3 = f2sub(t1, r);
    }
    {
        float2 t0 = f2add(v[1], v[5]), t1 = f2sub(v[1], v[5]);
        float2 t2 = f2add(v[3], v[7]), t3 = f2sub(v[3], v[7]);
        float2 r  = c_muli<S>(t3);
        o0 = f2add(t0, t2); o2 = f2sub(t0, t2); o1 = f2add(t1, r); o3 = f2sub(t1, r);
    }
    const float2 w1 = make_float2(RH,  (S > 0) ? RH : -RH);
    const float2 w3 = make_float2(-RH, (S > 0) ? RH : -RH);
    float2 a;
    v[0] = f2add(e0, o0); v[4] = f2sub(e0, o0);
    a = c_mul(o1, w1);    v[1] = f2add(e1, a); v[5] = f2sub(e1, a);
    a = c_muli<S>(o2);    v[2] = f2add(e2, a); v[6] = f2sub(e2, a);
    a = c_mul(o3, w3);    v[3] = f2add(e3, a); v[7] = f2sub(e3, a);
}

__device__ __forceinline__ float2 shflx2(float2 v, int m) {
    v.x = __shfl_xor_sync(0xffffffffu, v.x, m);
    v.y = __shfl_xor_sync(0xffffffffu, v.y, m);
    return v;
}

__device__ __forceinline__ void dif_stage(float2 x[8], int m, float2 w, bool up) {
    #pragma unroll
    for (int r = 0; r < 8; r++) {
        float2 o = shflx2(x[r], m);
        x[r] = up ? c_mul(f2sub(o, x[r]), w) : f2add(x[r], o);
    }
}
__device__ __forceinline__ void stage_m1(float2 x[8], bool up) {
    #pragma unroll
    for (int r = 0; r < 8; r++) {
        float2 o = shflx2(x[r], 1);
        x[r] = up ? f2sub(o, x[r]) : f2add(x[r], o);
    }
}
__device__ __forceinline__ void dit_stage(float2 x[8], int m, float2 wc, bool up) {
    #pragma unroll
    for (int r = 0; r < 8; r++) {
        float2 o  = shflx2(x[r], m);
        float2 vw = c_mul(up ? x[r] : o, wc);
        x[r] = up ? f2sub(o, vw) : f2add(x[r], vw);
    }
}

__device__ __forceinline__ void wsum8(float* v) {
    #pragma unroll
    for (int m = 16; m; m >>= 1) {
        #pragma unroll
        for (int j = 0; j < 8; j++) v[j] += __shfl_xor_sync(0xffffffffu, v[j], m);
    }
}

// ---- scan: 2 independent pairs per warp, segment loops FUSED (ILP-2 in the stall region) ----
#define RPW 4
#define SCAN_WARPS 8
__global__ void __launch_bounds__(256, 2) k_scan(const float* __restrict__ g1,
                                                 const float* __restrict__ be1,
                                                 const float* __restrict__ alphas,
                                                 const float* __restrict__ betas) {
    int warp = threadIdx.x >> 5, lane = threadIdx.x & 31;
    int row0 = (blockIdx.x * SCAN_WARPS + warp) * RPW;
    int rl = __brev((unsigned)lane) >> 27;
    const float sc = 0.031622776601683793f;

    int mrl   = (32 - rl) & 31;
    int mlane = (int)(__brev((unsigned)mrl) >> 27);

    bool u1 = (lane & 1), u2 = (lane & 2), u4 = (lane & 4), u8 = (lane & 8), u16 = (lane & 16);

    float2 A0[8], B0[8], A1[8], B1[8];

    // ---- load + BN + forward FFT + split, per pair (transient twiddles & BN coeffs) ----
    auto loadpair = [&](int rowa, float2* A, float2* B) {
        int rowb = rowa + 1;
        float2 Z[8];
        #pragma unroll
        for (int r = 0; r < 8; r++) {
            int c = lane + 32 * r;
            float gg = g1[c] * g_rs1[c];
            float bb = be1[c] - g1[c] * g_mu1[c] * g_rs1[c];
            float va = fmaxf(gg * g_z[(size_t)rowa * D_H + c] + bb, 0.f);
            float vb = fmaxf(gg * g_z[(size_t)rowb * D_H + c] + bb, 0.f);
            Z[r] = make_float2(va, vb);
        }
        {
            float2 W2t, W4t, W8t, W16t, Tf[8];
            float a;
            a = -2.f * PI_F * (float)(lane & 1)  / 4.f;   W2t  = make_float2(cosf(a), sinf(a));
            a = -2.f * PI_F * (float)(lane & 3)  / 8.f;   W4t  = make_float2(cosf(a), sinf(a));
            a = -2.f * PI_F * (float)(lane & 7)  / 16.f;  W8t  = make_float2(cosf(a), sinf(a));
            a = -2.f * PI_F * (float)(lane & 15) / 32.f;  W16t = make_float2(cosf(a), sinf(a));
            #pragma unroll
            for (int r = 0; r < 8; r++) {
                float t = -2.f * PI_F * (float)(lane * r) / 256.f;
                Tf[r] = make_float2(cosf(t), sinf(t));
            }
            fft8<-1>(Z);
            #pragma unroll
            for (int r = 0; r < 8; r++) Z[r] = c_mul(Z[r], Tf[r]);
            dif_stage(Z, 16, W16t, u16);
            dif_stage(Z, 8,  W8t,  u8);
            dif_stage(Z, 4,  W4t,  u4);
            dif_stage(Z, 2,  W2t,  u2);
            stage_m1(Z, u1);
        }
        float2 Zc[8];
        {
            float tx = __shfl_sync(0xffffffffu, Z[0].x, mlane);
            float ty = __shfl_sync(0xffffffffu, Z[0].y, mlane);
            Zc[0] = make_float2(tx, -ty);
        }
        #pragma unroll
        for (int r = 1; r < 8; r++) {
            float2 t = shflx2(Z[8 - r], 31);
            Zc[r] = make_float2(t.x, -t.y);
        }
        #pragma unroll
        for (int r = 0; r < 8; r++) {
            A[r] = make_float2(0.5f * (Z[r].x + Zc[r].x), 0.5f * (Z[r].y + Zc[r].y));
            float dx = Z[r].x - Zc[r].x, dy = Z[r].y - Zc[r].y;
            B[r] = make_float2(0.5f * dy, -0.5f * dx);
        }
    };
    loadpair(row0,     A0, B0);
    loadpair(row0 + 2, A1, B1);

    // ---- 20 fused diagonal segments: both pairs interleaved ----
    for (int seg = 0; seg < N_SEGS; seg++) {
        float2 Hs[8];
        float  H2[8];
        const float4* Hp = (const float4*)(g_He + seg * D_H + 8 * rl);
        #pragma unroll
        for (int r4 = 0; r4 < 4; r4++) {
            float4 hv = __ldg(Hp + r4);
            Hs[2 * r4]     = make_float2(hv.x, hv.y);
            Hs[2 * r4 + 1] = make_float2(hv.z, hv.w);
            H2[2 * r4]     = hv.x * hv.x + hv.y * hv.y;
            H2[2 * r4 + 1] = hv.z * hv.z + hv.w * hv.w;
        }

        float2 acc[8];   // sa0, ta0, sb0, tb0, sa1, ta1, sb1, tb1 (packed re/im)
        #pragma unroll
        for (int j = 0; j < 8; j++) acc[j] = make_float2(0.f, 0.f);
        #pragma unroll
        for (int r = 0; r < 8; r++) {
            float2 h2p = make_float2(H2[r], H2[r]);
            float2 pa0 = f2mul(A0[r], A0[r]);
            float2 pb0 = f2mul(B0[r], B0[r]);
            float2 pa1 = f2mul(A1[r], A1[r]);
            float2 pb1 = f2mul(B1[r], B1[r]);
            acc[0] = f2add(acc[0], pa0);
            acc[1] = f2fma(pa0, h2p, acc[1]);
            acc[2] = f2add(acc[2], pb0);
            acc[3] = f2fma(pb0, h2p, acc[3]);
            acc[4] = f2add(acc[4], pa1);
            acc[5] = f2fma(pa1, h2p, acc[5]);
            acc[6] = f2add(acc[6], pb1);
            acc[7] = f2fma(pb1, h2p, acc[7]);
        }
        float s[8];
        #pragma unroll
        for (int j = 0; j < 8; j++) s[j] = acc[j].x + acc[j].y;
        wsum8(s);

        float al = __ldg(alphas + seg), bt = __ldg(betas + seg);
        float g4[4];
        #pragma unroll
        for (int j = 0; j < 4; j++) {            // rows: a0, b0, a1, b1
            float n2 = s[2 * j]     * (1.f / 256.f);
            float c2 = s[2 * j + 1] * (1.f / 256.f);
            float sn = fminf(fmaxf(sc * sqrtf(n2), 1e-12f), 1.f - 1e-5f);
            float sl = fast_atanh_over_x(sn);
            float snv = fmaxf(sc * sl * sqrtf(c2), 1e-12f);
            g4[j] = al * fast_tanh_over_x(snv) * sl;
        }

        #pragma unroll
        for (int r = 0; r < 8; r++) {
            float2 Ka0 = make_float2(fmaf(g4[0], Hs[r].x, bt), g4[0] * Hs[r].y);
            float2 Kb0 = make_float2(fmaf(g4[1], Hs[r].x, bt), g4[1] * Hs[r].y);
            float2 Ka1 = make_float2(fmaf(g4[2], Hs[r].x, bt), g4[2] * Hs[r].y);
            float2 Kb1 = make_float2(fmaf(g4[3], Hs[r].x, bt), g4[3] * Hs[r].y);
            A0[r] = c_mul(Ka0, A0[r]);
            B0[r] = c_mul(Kb0, B0[r]);
            A1[r] = c_mul(Ka1, A1[r]);
            B1[r] = c_mul(Kb1, B1[r]);
        }
    }

    // ---- recombine + inverse FFT + store, per pair ----
    auto storepair = [&](int rowa, const float2* A, const float2* B) {
        int rowb = rowa + 1;
        float2 Z[8];
        #pragma unroll
        for (int r = 0; r < 8; r++)
            Z[r] = make_float2(A[r].x - B[r].y, A[r].y + B[r].x);

        float2 W2t, W4t, W8t, W16t, Tf[8];
        float a;
        a = 2.f * PI_F * (float)(lane & 1)  / 4.f;   W2t  = make_float2(cosf(a), sinf(a));
        a = 2.f * PI_F * (float)(lane & 3)  / 8.f;   W4t  = make_float2(cosf(a), sinf(a));
        a = 2.f * PI_F * (float)(lane & 7)  / 16.f;  W8t  = make_float2(cosf(a), sinf(a));
        a = 2.f * PI_F * (float)(lane & 15) / 32.f;  W16t = make_float2(cosf(a), sinf(a));
        #pragma unroll
        for (int r = 0; r < 8; r++) {
            float t = 2.f * PI_F * (float)(lane * r) / 256.f;
            Tf[r] = make_float2(cosf(t), sinf(t));
        }
        stage_m1(Z, u1);
        dit_stage(Z, 2,  W2t,  u2);
        dit_stage(Z, 4,  W4t,  u4);
        dit_stage(Z, 8,  W8t,  u8);
        dit_stage(Z, 16, W16t, u16);
        #pragma unroll
        for (int r = 0; r < 8; r++) Z[r] = c_mul(Z[r], Tf[r]);
        fft8<1>(Z);

        const float2 i256 = make_float2(1.f / 256.f, 1.f / 256.f);
        #pragma unroll
        for (int r = 0; r < 8; r++) {
            float2 hp = f2mul(Z[r], i256);
            int c = lane + 32 * r;
            g_h2[(size_t)rowa * D_H + c] = hp.x;
            g_h2[(size_t)rowb * D_H + c] = hp.y;
        }
    };
    storepair(row0,     A0, B0);
    storepair(row0 + 2, A1, B1);
}

// ---------------- final: out = relu(BN2(h2)) @ W2 + b2 ----------------
__global__ __launch_bounds__(256) void k_out(const float* __restrict__ g2,
                                             const float* __restrict__ be2,
                                             const float* __restrict__ W2,
                                             const float* __restrict__ b2,
                                             float* __restrict__ out) {
    __shared__ float sW[D_H * D_OUT];
    for (int i = threadIdx.x; i < D_H * D_OUT; i += 256) sW[i] = W2[i];
    __syncthreads();
    int warp = threadIdx.x >> 5, lane = threadIdx.x & 31;
    int row = blockIdx.x * 8 + warp;
    float acc[D_OUT];
    #pragma unroll
    for (int o = 0; o < D_OUT; o++) acc[o] = 0.f;
    #pragma unroll
    for (int r = 0; r < 8; r++) {
        int c = lane + 32 * r;
        float hv = g_h2[(size_t)row * D_H + c];
        float a  = fmaxf(g2[c] * (hv - g_mu2[c]) * g_rs2[c] + be2[c], 0.f);
        #pragma unroll
        for (int o = 0; o < D_OUT; o++) acc[o] += a * sW[c * D_OUT + o];
    }
    #pragma unroll
    for (int o = 0; o < D_OUT; o++) {
        #pragma unroll
        for (int m = 16; m; m >>= 1) acc[o] += __shfl_xor_sync(0xffffffffu, acc[o], m);
    }
    if (lane < D_OUT) out[(size_t)row * D_OUT + lane] = acc[lane] + b2[lane];
}

// ---------------- launch ----------------
extern "C" void kernel_launch(void* const* d_in, const int* in_sizes, int n_in,
                              void* d_out, int out_size) {
    const float* x   = (const float*)d_in[0];
    const float* W1  = (const float*)d_in[1];
    const float* b1  = (const float*)d_in[2];
    const float* g1  = (const float*)d_in[3];
    const float* be1 = (const float*)d_in[4];
    const float* Hr  = (const float*)d_in[5];
    const float* Hi  = (const float*)d_in[6];
    const float* al  = (const float*)d_in[7];
    const float* bt  = (const float*)d_in[8];
    const float* g2  = (const float*)d_in[9];
    const float* be2 = (const float*)d_in[10];
    const float* W2  = (const float*)d_in[11];
    const float* b2  = (const float*)d_in[12];
    float* out = (float*)d_out;

    cudaFuncSetAttribute(k_gemm_mma, cudaFuncAttributeMaxDynamicSharedMemorySize, SMEM_G);

    k_prep_all<<<49 + N_SEGS, D_H>>>(W1, Hr, Hi);            // launch 1
    k_gemm_mma<<<B_ROWS / 64, 256, SMEM_G>>>(x, b1);         // launch 2
    k_bnreduce<<<1, 1024>>>(1, 512);                         // launch 3
    k_scan<<<B_ROWS / (SCAN_WARPS * RPW), 256>>>(g1, be1, al, bt);  // launch 4 (captured)
    k_stats2<<<256, 256>>>();                                // launch 5
    k_bnreduce<<<1, 1024>>>(2, 256);                         // launch 6
    k_out<<<B_ROWS / 8, 256>>>(g2, be2, W2, b2, out);        // launch 7
}

// round 16
// speedup vs baseline: 1.1290x; 1.0588x over previous
#include <cuda_runtime.h>
#include <cuda_bf16.h>
#include <math.h>
#include <stdint.h>

#define B_ROWS 32768
#define D_IN   784
#define D_H    256
#define D_OUT  10
#define N_SEGS 20
#define SEG_E  50
#define PI_F   3.14159265358979323846f

// ---------------- scratch (static __device__ arrays: allocation-free) ----------------
__device__ float  g_z  [B_ROWS * D_H];
__device__ float  g_h2 [B_ROWS * D_H];
__device__ float2 g_He [N_SEGS * D_H];   // Hermitian-symmetrized (hr + i*hi)^50
__device__ float  g_p1 [2 * 512 * D_H];
__device__ float  g_p2 [2 * 512 * D_H];
__device__ float  g_mu1[D_H], g_rs1[D_H], g_mu2[D_H], g_rs2[D_H];
__device__ __align__(16) unsigned short g_Bhi[D_H * D_IN];
__device__ __align__(16) unsigned short g_Blo[D_H * D_IN];

// ---------------- packed f32x2 helpers ----------------
__device__ __forceinline__ float2 f2add(float2 a, float2 b) {
    union { float2 f; unsigned long long u; } A, B, R;
    A.f = a; B.f = b;
    asm("add.rn.f32x2 %0, %1, %2;" : "=l"(R.u) : "l"(A.u), "l"(B.u));
    return R.f;
}
__device__ __forceinline__ float2 f2mul(float2 a, float2 b) {
    union { float2 f; unsigned long long u; } A, B, R;
    A.f = a; B.f = b;
    asm("mul.rn.f32x2 %0, %1, %2;" : "=l"(R.u) : "l"(A.u), "l"(B.u));
    return R.f;
}
__device__ __forceinline__ float2 f2fma(float2 a, float2 b, float2 c) {
    union { float2 f; unsigned long long u; } A, B, C, R;
    A.f = a; B.f = b; C.f = c;
    asm("fma.rn.f32x2 %0, %1, %2, %3;" : "=l"(R.u) : "l"(A.u), "l"(B.u), "l"(C.u));
    return R.f;
}
__device__ __forceinline__ float2 f2sub(float2 a, float2 b) {
    union { float2 f; unsigned long long u; } A, B, R;
    A.f = a; B.f = b;
    const unsigned long long NEG1 = 0xBF800000BF800000ULL;
    asm("fma.rn.f32x2 %0, %1, %2, %3;" : "=l"(R.u) : "l"(B.u), "l"(NEG1), "l"(A.u));
    return R.f;
}

// ---------------- fast transcendentals ----------------
__device__ __forceinline__ float fast_atanh_over_x(float x) {
    float x2 = x * x;
    float small = 1.f + x2 * (1.f / 3.f) + x2 * x2 * 0.2f;
    float big = 0.5f * __logf(__fdividef(1.f + x, 1.f - x));
    big = __fdividef(big, x);
    return (x < 0.03f) ? small : big;
}
__device__ __forceinline__ float fast_tanh_over_x(float x) {
    float x2 = x * x;
    float small = 1.f - x2 * (1.f / 3.f) + x2 * x2 * (2.f / 15.f);
    float e = __expf(2.f * fminf(x, 15.f));
    float big = __fdividef(e - 1.f, (e + 1.f) * x);
    return (x < 0.03f) ? small : big;
}

// ------- merged prep: blocks 0-48 split W1; blocks 49-68 build Hs -------
__global__ void k_prep_all(const float* __restrict__ W1,
                           const float* __restrict__ Hr,
                           const float* __restrict__ Hi) {
    if (blockIdx.x < 49) {
        int n = threadIdx.x;
        int k0 = blockIdx.x * 16;
        unsigned short h[16], l[16];
        #pragma unroll
        for (int kk = 0; kk < 16; kk++) {
            float w = W1[(size_t)(k0 + kk) * D_H + n];
            __nv_bfloat16 bh = __float2bfloat16_rn(w);
            float r = w - __bfloat162float(bh);
            h[kk] = __bfloat16_as_ushort(bh);
            l[kk] = __bfloat16_as_ushort(__float2bfloat16_rn(r));
        }
        uint32_t* ph = (uint32_t*)(g_Bhi + (size_t)n * D_IN + k0);
        uint32_t* pl = (uint32_t*)(g_Blo + (size_t)n * D_IN + k0);
        #pragma unroll
        for (int j = 0; j < 8; j++) {
            ph[j] = (uint32_t)h[2*j] | ((uint32_t)h[2*j+1] << 16);
            pl[j] = (uint32_t)l[2*j] | ((uint32_t)l[2*j+1] << 16);
        }
    } else {
        __shared__ float2 E[D_H];
        int seg = blockIdx.x - 49, k = threadIdx.x;
        int i = seg * D_H + k;
        float br = Hr[i], bi = Hi[i], ar = 1.f, ai = 0.f;
        int e = SEG_E;
        while (e) {
            if (e & 1) { float t = ar*br - ai*bi; ai = ar*bi + ai*br; ar = t; }
            e >>= 1;
            if (e) { float t = br*br - bi*bi; bi = 2.f*br*bi; br = t; }
        }
        E[k] = make_float2(ar, ai);
        __syncthreads();
        float2 ek = E[k];
        float2 er = E[(D_H - k) & (D_H - 1)];
        g_He[i] = make_float2(0.5f * (ek.x + er.x), 0.5f * (ek.y - er.y));
    }
}

// ======= mma.sync GEMM1: K=16 panels, low staging regs, 2 CTAs/SM =======
#define RSTR 48                           // 16 bf16 = 32 B + 16 pad
#define OFF_AHI 0                         // 64 * 48  = 3072
#define OFF_ALO 3072
#define OFF_BHI 6144                      // 256 * 48 = 12288
#define OFF_BLO 18432
#define STAGE   30720
#define SMEM_G  (2 * STAGE)
#define NPANEL  49

__device__ __forceinline__ void ldsm4(uint32_t* r, uint32_t a) {
    asm volatile("ldmatrix.sync.aligned.m8n8.x4.shared.b16 {%0,%1,%2,%3}, [%4];"
        : "=r"(r[0]), "=r"(r[1]), "=r"(r[2]), "=r"(r[3]) : "r"(a));
}
__device__ __forceinline__ void mma16816(float* c, const uint32_t* a, uint32_t b0, uint32_t b1) {
    asm volatile("mma.sync.aligned.m16n8k16.row.col.f32.bf16.bf16.f32 "
        "{%0,%1,%2,%3}, {%4,%5,%6,%7}, {%8,%9}, {%0,%1,%2,%3};"
        : "+f"(c[0]), "+f"(c[1]), "+f"(c[2]), "+f"(c[3])
        : "r"(a[0]), "r"(a[1]), "r"(a[2]), "r"(a[3]), "r"(b0), "r"(b1));
}
__device__ __forceinline__ uint32_t split2(float x, float y, uint32_t& lo) {
    __nv_bfloat16 hx = __float2bfloat16_rn(x), hy = __float2bfloat16_rn(y);
    __nv_bfloat16 lx = __float2bfloat16_rn(x - __bfloat162float(hx));
    __nv_bfloat16 ly = __float2bfloat16_rn(y - __bfloat162float(hy));
    lo = (uint32_t)__bfloat16_as_ushort(lx) | ((uint32_t)__bfloat16_as_ushort(ly) << 16);
    return (uint32_t)__bfloat16_as_ushort(hx) | ((uint32_t)__bfloat16_as_ushort(hy) << 16);
}
__device__ __forceinline__ uint32_t smem_u32(const void* p) {
    uint32_t a;
    asm("{ .reg .u64 t; cvta.to.shared.u64 t, %1; cvt.u32.u64 %0, t; }" : "=r"(a) : "l"(p));
    return a;
}

__global__ void __launch_bounds__(256, 2) k_gemm_mma(const float* __restrict__ A,
                                                     const float* __restrict__ bias) {
    extern __shared__ char sm[];
    uint32_t sbase = smem_u32(sm);
    int tid = threadIdx.x, warp = tid >> 5, lane = tid & 31;
    int wm = warp >> 2, wn = warp & 3;
    int gid = lane >> 2, tqd = lane & 3;

    const float* Ab = A + (size_t)blockIdx.x * 64 * D_IN;

    float c[2][8][4];
    #pragma unroll
    for (int mt = 0; mt < 2; mt++)
        #pragma unroll
        for (int nt = 0; nt < 8; nt++)
            #pragma unroll
            for (int r = 0; r < 4; r++) c[mt][nt][r] = 0.f;

    float4 pa;            // A stage: 64 rows x 16 f32 / 256 thr = 4 f32
    uint4  pbh[2], pbl[2];// B stage: row tid, 16 ushort = 2 x uint4 each

    auto prefetch = [&](int p) {
        int k0 = p * 16;
        int r = tid >> 2, c4 = (tid & 3) * 4;
        pa = *(const float4*)(Ab + (size_t)r * D_IN + k0 + c4);
        #pragma unroll
        for (int j = 0; j < 2; j++) {
            pbh[j] = *(const uint4*)(g_Bhi + (size_t)tid * D_IN + k0 + j * 8);
            pbl[j] = *(const uint4*)(g_Blo + (size_t)tid * D_IN + k0 + j * 8);
        }
    };
    auto store_panel = [&](int b) {
        char* s = sm + b * STAGE;
        int r = tid >> 2, c4 = (tid & 3) * 4;
        uint32_t l0, l1, h0, h1;
        h0 = split2(pa.x, pa.y, l0);
        h1 = split2(pa.z, pa.w, l1);
        uint32_t offA = (uint32_t)(r * RSTR + c4 * 2);
        *(uint2*)(s + OFF_AHI + offA) = make_uint2(h0, h1);
        *(uint2*)(s + OFF_ALO + offA) = make_uint2(l0, l1);
        #pragma unroll
        for (int j = 0; j < 2; j++) {
            uint32_t offB = (uint32_t)(tid * RSTR + j * 16);
            *(uint4*)(s + OFF_BHI + offB) = pbh[j];
            *(uint4*)(s + OFF_BLO + offB) = pbl[j];
        }
    };
    auto mma_panel = [&](int b) {
        uint32_t base = sbase + b * STAGE;
        uint32_t ah[2][4], al[2][4];
        #pragma unroll
        for (int mt = 0; mt < 2; mt++) {
            uint32_t off = (uint32_t)((wm * 32 + mt * 16 + (lane & 15)) * RSTR
                                      + ((lane >> 4) << 4));
            ldsm4(ah[mt], base + OFF_AHI + off);
            ldsm4(al[mt], base + OFF_ALO + off);
        }
        uint32_t bh[4][4], bl[4][4];
        #pragma unroll
        for (int q = 0; q < 4; q++) {
            int nrow = wn * 64 + q * 16 + (lane & 7) + ((lane >> 4) << 3);
            uint32_t off = (uint32_t)(nrow * RSTR + (((lane >> 3) & 1) << 4));
            ldsm4(bh[q], base + OFF_BHI + off);
            ldsm4(bl[q], base + OFF_BLO + off);
        }
        #pragma unroll
        for (int mt = 0; mt < 2; mt++)
            #pragma unroll
            for (int q = 0; q < 4; q++) {
                mma16816(c[mt][2*q],   ah[mt], bh[q][0], bh[q][1]);
                mma16816(c[mt][2*q+1], ah[mt], bh[q][2], bh[q][3]);
                mma16816(c[mt][2*q],   ah[mt], bl[q][0], bl[q][1]);
                mma16816(c[mt][2*q+1], ah[mt], bl[q][2], bl[q][3]);
                mma16816(c[mt][2*q],   al[mt], bh[q][0], bh[q][1]);
                mma16816(c[mt][2*q+1], al[mt], bh[q][2], bh[q][3]);
            }
    };

    prefetch(0);
    store_panel(0);
    __syncthreads();
    for (int p = 0; p < NPANEL; p++) {
        if (p + 1 < NPANEL) prefetch(p + 1);
        mma_panel(p & 1);
        if (p + 1 < NPANEL) store_panel((p + 1) & 1);
        __syncthreads();
    }

    // epilogue: z = acc + bias, fused per-block BN1 column partials
    float* stS = (float*)sm;
    float* stQ = stS + 512;
    int rowb0 = blockIdx.x * 64 + wm * 32;
    #pragma unroll
    for (int nt = 0; nt < 8; nt++) {
        int col = wn * 64 + nt * 8 + tqd * 2;
        float bx = bias[col], by = bias[col + 1];
        float vs0 = 0.f, vs1 = 0.f, q0 = 0.f, q1 = 0.f;
        #pragma unroll
        for (int mt = 0; mt < 2; mt++) {
            int r0 = rowb0 + mt * 16 + gid;
            float v0 = c[mt][nt][0] + bx, v1 = c[mt][nt][1] + by;
            float v2 = c[mt][nt][2] + bx, v3 = c[mt][nt][3] + by;
            *(float2*)&g_z[(size_t)r0 * D_H + col]       = make_float2(v0, v1);
            *(float2*)&g_z[(size_t)(r0 + 8) * D_H + col] = make_float2(v2, v3);
            vs0 += v0 + v2; vs1 += v1 + v3;
            q0 += v0 * v0 + v2 * v2; q1 += v1 * v1 + v3 * v3;
        }
        #pragma unroll
        for (int m = 4; m <= 16; m <<= 1) {
            vs0 += __shfl_xor_sync(0xffffffffu, vs0, m);
            vs1 += __shfl_xor_sync(0xffffffffu, vs1, m);
            q0  += __shfl_xor_sync(0xffffffffu, q0,  m);
            q1  += __shfl_xor_sync(0xffffffffu, q1,  m);
        }
        if (gid == 0) {
            stS[wm * 256 + col] = vs0; stS[wm * 256 + col + 1] = vs1;
            stQ[wm * 256 + col] = q0;  stQ[wm * 256 + col + 1] = q1;
        }
    }
    __syncthreads();
    if (tid < 256) {
        g_p1[(size_t)blockIdx.x * D_H + tid]         = stS[tid] + stS[256 + tid];
        g_p1[(size_t)(512 + blockIdx.x) * D_H + tid] = stQ[tid] + stQ[256 + tid];
    }
}

// ---------------- BN2 column-stat partials over h2 ----------------
__global__ void k_stats2() {
    int col = threadIdx.x, b = blockIdx.x;
    float s = 0.f, q = 0.f;
    const float* p = g_h2 + (size_t)b * 128 * D_H + col;
    for (int r = 0; r < 128; r++) { float v = p[(size_t)r * D_H]; s += v; q += v * v; }
    g_p2[b * D_H + col]         = s;
    g_p2[(256 + b) * D_H + col] = q;
}

// ---------------- fused deterministic BN reduce (single launch) ----------------
__global__ void k_bnreduce(int which, int nblk) {
    __shared__ float sS[4][D_H], sQ[4][D_H];
    const float* part = (which == 1) ? g_p1 : g_p2;
    int col = threadIdx.x & 255, grp = threadIdx.x >> 8;
    int per = nblk / 4;
    float s = 0.f, q = 0.f;
    for (int b = grp * per; b < (grp + 1) * per; b++) {
        s += part[b * D_H + col];
        q += part[(nblk + b) * D_H + col];
    }
    sS[grp][col] = s; sQ[grp][col] = q;
    __syncthreads();
    if (threadIdx.x < 256) {
        float S = sS[0][col] + sS[1][col] + sS[2][col] + sS[3][col];
        float Q = sQ[0][col] + sQ[1][col] + sQ[2][col] + sQ[3][col];
        float m   = S * (1.0f / B_ROWS);
        float var = Q * (1.0f / B_ROWS) - m * m;
        float rs  = rsqrtf(var + 1e-5f);
        if (which == 1) { g_mu1[col] = m; g_rs1[col] = rs; }
        else            { g_mu2[col] = m; g_rs2[col] = rs; }
    }
}

// ---------------- complex helpers ----------------
__device__ __forceinline__ float2 c_mul(float2 a, float2 b){ return make_float2(a.x*b.x - a.y*b.y, a.x*b.y + a.y*b.x); }

template <int S>
__device__ __forceinline__ float2 c_muli(float2 a) {
    return (S > 0) ? make_float2(-a.y, a.x) : make_float2(a.y, -a.x);
}

template <int S>
__device__ __forceinline__ void fft8(float2 v[8]) {
    const float RH = 0.70710678118654752f;
    float2 e0, e1, e2, e3, o0, o1, o2, o3;
    {
        float2 t0 = f2add(v[0], v[4]), t1 = f2sub(v[0], v[4]);
        float2 t2 = f2add(v[2], v[6]), t3 = f2sub(v[2], v[6]);
        float2 r  = c_muli<S>(t3);
        e0 = f2add(t0, t2); e2 = f2sub(t0, t2); e1 = f2add(t1, r); e3 = f2sub(t1, r);
    }
    {
        float2 t0 = f2add(v[1], v[5]), t1 = f2sub(v[1], v[5]);
        float2 t2 = f2add(v[3], v[7]), t3 = f2sub(v[3], v[7]);
        float2 r  = c_muli<S>(t3);
        o0 = f2add(t0, t2); o2 = f2sub(t0, t2); o1 = f2add(t1, r); o3 = f2sub(t1, r);
    }
    const float2 w1 = make_float2(RH,  (S > 0) ? RH : -RH);
    const float2 w3 = make_float2(-RH, (S > 0) ? RH : -RH);
    float2 a;
    v[0] = f2add(e0, o0); v[4] = f2sub(e0, o0);
    a = c_mul(o1, w1);    v[1] = f2add(e1, a); v[5] = f2sub(e1, a);
    a = c_muli<S>(o2);    v[2] = f2add(e2, a); v[6] = f2sub(e2, a);
    a = c_mul(o3, w3);    v[3] = f2add(e3, a); v[7] = f2sub(e3, a);
}

__device__ __forceinline__ float2 shflx2(float2 v, int m) {
    v.x = __shfl_xor_sync(0xffffffffu, v.x, m);
    v.y = __shfl_xor_sync(0xffffffffu, v.y, m);
    return v;
}

__device__ __forceinline__ void dif_stage(float2 x[8], int m, float2 w, bool up) {
    #pragma unroll
    for (int r = 0; r < 8; r++) {
        float2 o = shflx2(x[r], m);
        x[r] = up ? c_mul(f2sub(o, x[r]), w) : f2add(x[r], o);
    }
}
__device__ __forceinline__ void stage_m1(float2 x[8], bool up) {
    #pragma unroll
    for (int r = 0; r < 8; r++) {
        float2 o = shflx2(x[r], 1);
        x[r] = up ? f2sub(o, x[r]) : f2add(x[r], o);
    }
}
__device__ __forceinline__ void dit_stage(float2 x[8], int m, float2 wc, bool up) {
    #pragma unroll
    for (int r = 0; r < 8; r++) {
        float2 o  = shflx2(x[r], m);
        float2 vw = c_mul(up ? x[r] : o, wc);
        x[r] = up ? f2sub(o, vw) : f2add(x[r], vw);
    }
}

__device__ __forceinline__ void wsum8(float* v) {
    #pragma unroll
    for (int m = 16; m; m >>= 1) {
        #pragma unroll
        for (int j = 0; j < 8; j++) v[j] += __shfl_xor_sync(0xffffffffu, v[j], m);
    }
}

// ---- scan: 2 independent pairs per warp, segment loops FUSED (R15 config) ----
#define RPW 4
#define SCAN_WARPS 8
__global__ void __launch_bounds__(256, 2) k_scan(const float* __restrict__ g1,
                                                 const float* __restrict__ be1,
                                                 const float* __restrict__ alphas,
                                                 const float* __restrict__ betas) {
    int warp = threadIdx.x >> 5, lane = threadIdx.x & 31;
    int row0 = (blockIdx.x * SCAN_WARPS + warp) * RPW;
    int rl = __brev((unsigned)lane) >> 27;
    const float sc = 0.031622776601683793f;

    int mrl   = (32 - rl) & 31;
    int mlane = (int)(__brev((unsigned)mrl) >> 27);

    bool u1 = (lane & 1), u2 = (lane & 2), u4 = (lane & 4), u8 = (lane & 8), u16 = (lane & 16);

    float2 A0[8], B0[8], A1[8], B1[8];

    auto loadpair = [&](int rowa, float2* A, float2* B) {
        int rowb = rowa + 1;
        float2 Z[8];
        #pragma unroll
        for (int r = 0; r < 8; r++) {
            int c = lane + 32 * r;
            float gg = g1[c] * g_rs1[c];
            float bb = be1[c] - g1[c] * g_mu1[c] * g_rs1[c];
            float va = fmaxf(gg * g_z[(size_t)rowa * D_H + c] + bb, 0.f);
            float vb = fmaxf(gg * g_z[(size_t)rowb * D_H + c] + bb, 0.f);
            Z[r] = make_float2(va, vb);
        }
        {
            float2 W2t, W4t, W8t, W16t, Tf[8];
            float a;
            a = -2.f * PI_F * (float)(lane & 1)  / 4.f;   W2t  = make_float2(cosf(a), sinf(a));
            a = -2.f * PI_F * (float)(lane & 3)  / 8.f;   W4t  = make_float2(cosf(a), sinf(a));
            a = -2.f * PI_F * (float)(lane & 7)  / 16.f;  W8t  = make_float2(cosf(a), sinf(a));
            a = -2.f * PI_F * (float)(lane & 15) / 32.f;  W16t = make_float2(cosf(a), sinf(a));
            #pragma unroll
            for (int r = 0; r < 8; r++) {
                float t = -2.f * PI_F * (float)(lane * r) / 256.f;
                Tf[r] = make_float2(cosf(t), sinf(t));
            }
            fft8<-1>(Z);
            #pragma unroll
            for (int r = 0; r < 8; r++) Z[r] = c_mul(Z[r], Tf[r]);
            dif_stage(Z, 16, W16t, u16);
            dif_stage(Z, 8,  W8t,  u8);
            dif_stage(Z, 4,  W4t,  u4);
            dif_stage(Z, 2,  W2t,  u2);
            stage_m1(Z, u1);
        }
        float2 Zc[8];
        {
            float tx = __shfl_sync(0xffffffffu, Z[0].x, mlane);
            float ty = __shfl_sync(0xffffffffu, Z[0].y, mlane);
            Zc[0] = make_float2(tx, -ty);
        }
        #pragma unroll
        for (int r = 1; r < 8; r++) {
            float2 t = shflx2(Z[8 - r], 31);
            Zc[r] = make_float2(t.x, -t.y);
        }
        #pragma unroll
        for (int r = 0; r < 8; r++) {
            A[r] = make_float2(0.5f * (Z[r].x + Zc[r].x), 0.5f * (Z[r].y + Zc[r].y));
            float dx = Z[r].x - Zc[r].x, dy = Z[r].y - Zc[r].y;
            B[r] = make_float2(0.5f * dy, -0.5f * dx);
        }
    };
    loadpair(row0,     A0, B0);
    loadpair(row0 + 2, A1, B1);

    for (int seg = 0; seg < N_SEGS; seg++) {
        float2 Hs[8];
        float  H2[8];
        const float4* Hp = (const float4*)(g_He + seg * D_H + 8 * rl);
        #pragma unroll
        for (int r4 = 0; r4 < 4; r4++) {
            float4 hv = __ldg(Hp + r4);
            Hs[2 * r4]     = make_float2(hv.x, hv.y);
            Hs[2 * r4 + 1] = make_float2(hv.z, hv.w);
            H2[2 * r4]     = hv.x * hv.x + hv.y * hv.y;
            H2[2 * r4 + 1] = hv.z * hv.z + hv.w * hv.w;
        }

        float2 acc[8];
        #pragma unroll
        for (int j = 0; j < 8; j++) acc[j] = make_float2(0.f, 0.f);
        #pragma unroll
        for (int r = 0; r < 8; r++) {
            float2 h2p = make_float2(H2[r], H2[r]);
            float2 pa0 = f2mul(A0[r], A0[r]);
            float2 pb0 = f2mul(B0[r], B0[r]);
            float2 pa1 = f2mul(A1[r], A1[r]);
            float2 pb1 = f2mul(B1[r], B1[r]);
            acc[0] = f2add(acc[0], pa0);
            acc[1] = f2fma(pa0, h2p, acc[1]);
            acc[2] = f2add(acc[2], pb0);
            acc[3] = f2fma(pb0, h2p, acc[3]);
            acc[4] = f2add(acc[4], pa1);
            acc[5] = f2fma(pa1, h2p, acc[5]);
            acc[6] = f2add(acc[6], pb1);
            acc[7] = f2fma(pb1, h2p, acc[7]);
        }
        float s[8];
        #pragma unroll
        for (int j = 0; j < 8; j++) s[j] = acc[j].x + acc[j].y;
        wsum8(s);

        float al = __ldg(alphas + seg), bt = __ldg(betas + seg);
        float g4[4];
        #pragma unroll
        for (int j = 0; j < 4; j++) {
            float n2 = s[2 * j]     * (1.f / 256.f);
            float c2 = s[2 * j + 1] * (1.f / 256.f);
            float sn = fminf(fmaxf(sc * sqrtf(n2), 1e-12f), 1.f - 1e-5f);
            float sl = fast_atanh_over_x(sn);
            float snv = fmaxf(sc * sl * sqrtf(c2), 1e-12f);
            g4[j] = al * fast_tanh_over_x(snv) * sl;
        }

        #pragma unroll
        for (int r = 0; r < 8; r++) {
            float2 Ka0 = make_float2(fmaf(g4[0], Hs[r].x, bt), g4[0] * Hs[r].y);
            float2 Kb0 = make_float2(fmaf(g4[1], Hs[r].x, bt), g4[1] * Hs[r].y);
            float2 Ka1 = make_float2(fmaf(g4[2], Hs[r].x, bt), g4[2] * Hs[r].y);
            float2 Kb1 = make_float2(fmaf(g4[3], Hs[r].x, bt), g4[3] * Hs[r].y);
            A0[r] = c_mul(Ka0, A0[r]);
            B0[r] = c_mul(Kb0, B0[r]);
            A1[r] = c_mul(Ka1, A1[r]);
            B1[r] = c_mul(Kb1, B1[r]);
        }
    }

    auto storepair = [&](int rowa, const float2* A, const float2* B) {
        int rowb = rowa + 1;
        float2 Z[8];
        #pragma unroll
        for (int r = 0; r < 8; r++)
            Z[r] = make_float2(A[r].x - B[r].y, A[r].y + B[r].x);

        float2 W2t, W4t, W8t, W16t, Tf[8];
        float a;
        a = 2.f * PI_F * (float)(lane & 1)  / 4.f;   W2t  = make_float2(cosf(a), sinf(a));
        a = 2.f * PI_F * (float)(lane & 3)  / 8.f;   W4t  = make_float2(cosf(a), sinf(a));
        a = 2.f * PI_F * (float)(lane & 7)  / 16.f;  W8t  = make_float2(cosf(a), sinf(a));
        a = 2.f * PI_F * (float)(lane & 15) / 32.f;  W16t = make_float2(cosf(a), sinf(a));
        #pragma unroll
        for (int r = 0; r < 8; r++) {
            float t = 2.f * PI_F * (float)(lane * r) / 256.f;
            Tf[r] = make_float2(cosf(t), sinf(t));
        }
        stage_m1(Z, u1);
        dit_stage(Z, 2,  W2t,  u2);
        dit_stage(Z, 4,  W4t,  u4);
        dit_stage(Z, 8,  W8t,  u8);
        dit_stage(Z, 16, W16t, u16);
        #pragma unroll
        for (int r = 0; r < 8; r++) Z[r] = c_mul(Z[r], Tf[r]);
        fft8<1>(Z);

        const float2 i256 = make_float2(1.f / 256.f, 1.f / 256.f);
        #pragma unroll
        for (int r = 0; r < 8; r++) {
            float2 hp = f2mul(Z[r], i256);
            int c = lane + 32 * r;
            g_h2[(size_t)rowa * D_H + c] = hp.x;
            g_h2[(size_t)rowb * D_H + c] = hp.y;
        }
    };
    storepair(row0,     A0, B0);
    storepair(row0 + 2, A1, B1);
}

// ---------------- final: out = relu(BN2(h2)) @ W2 + b2 ----------------
__global__ __launch_bounds__(256) void k_out(const float* __restrict__ g2,
                                             const float* __restrict__ be2,
                                             const float* __restrict__ W2,
                                             const float* __restrict__ b2,
                                             float* __restrict__ out) {
    __shared__ float sW[D_H * D_OUT];
    for (int i = threadIdx.x; i < D_H * D_OUT; i += 256) sW[i] = W2[i];
    __syncthreads();
    int warp = threadIdx.x >> 5, lane = threadIdx.x & 31;
    int row = blockIdx.x * 8 + warp;
    float acc[D_OUT];
    #pragma unroll
    for (int o = 0; o < D_OUT; o++) acc[o] = 0.f;
    #pragma unroll
    for (int r = 0; r < 8; r++) {
        int c = lane + 32 * r;
        float hv = g_h2[(size_t)row * D_H + c];
        float a  = fmaxf(g2[c] * (hv - g_mu2[c]) * g_rs2[c] + be2[c], 0.f);
        #pragma unroll
        for (int o = 0; o < D_OUT; o++) acc[o] += a * sW[c * D_OUT + o];
    }
    #pragma unroll
    for (int o = 0; o < D_OUT; o++) {
        #pragma unroll
        for (int m = 16; m; m >>= 1) acc[o] += __shfl_xor_sync(0xffffffffu, acc[o], m);
    }
    if (lane < D_OUT) out[(size_t)row * D_OUT + lane] = acc[lane] + b2[lane];
}

// ---------------- launch ----------------
extern "C" void kernel_launch(void* const* d_in, const int* in_sizes, int n_in,
                              void* d_out, int out_size) {
    const float* x   = (const float*)d_in[0];
    const float* W1  = (const float*)d_in[1];
    const float* b1  = (const float*)d_in[2];
    const float* g1  = (const float*)d_in[3];
    const float* be1 = (const float*)d_in[4];
    const float* Hr  = (const float*)d_in[5];
    const float* Hi  = (const float*)d_in[6];
    const float* al  = (const float*)d_in[7];
    const float* bt  = (const float*)d_in[8];
    const float* g2  = (const float*)d_in[9];
    const float* be2 = (const float*)d_in[10];
    const float* W2  = (const float*)d_in[11];
    const float* b2  = (const float*)d_in[12];
    float* out = (float*)d_out;

    cudaFuncSetAttribute(k_gemm_mma, cudaFuncAttributeMaxDynamicSharedMemorySize, SMEM_G);

    k_prep_all<<<49 + N_SEGS, D_H>>>(W1, Hr, Hi);            // launch 1
    k_gemm_mma<<<B_ROWS / 64, 256, SMEM_G>>>(x, b1);         // launch 2
    k_bnreduce<<<1, 1024>>>(1, 512);                         // launch 3
    k_scan<<<B_ROWS / (SCAN_WARPS * RPW), 256>>>(g1, be1, al, bt);  // launch 4 (captured)
    k_stats2<<<256, 256>>>();                                // launch 5
    k_bnreduce<<<1, 1024>>>(2, 256);                         // launch 6
    k_out<<<B_ROWS / 8, 256>>>(g2, be2, W2, b2, out);        // launch 7
}